// round 15
// baseline (speedup 1.0000x reference)
#include <cuda_runtime.h>
#include <cuda_fp16.h>
#include <cstdint>

#define NNODES 100000
#define NPAD   100096          // multiple of 128; 100096/64 = 1564 blocks
#define HDIM   128
#define RWS    10
#define KHOPS  4
#define CDIM   40
#define NSAMP  (KHOPS * RWS)   // 40
#define ANPB   8               // nodes per agg block (1 warp per node)

// Scratch buffers — __device__ globals (zero-init).
__device__ __half g_bufA[(size_t)NPAD * HDIM];
__device__ __half g_bufB[(size_t)NPAD * HDIM];
__device__ __half g_w0h[256 * 128];
__device__ __half g_w1h[128 * 128];
__device__ float  g_sdeg[NNODES];    // sqrt(deg)
__device__ float  g_isdeg[NNODES];   // rsqrt(deg)

// ---------------------------------------------------------------------------
// Tensor-core + async-copy primitives
// ---------------------------------------------------------------------------
__device__ __forceinline__ uint32_t smem_u32(const void* p) {
    return (uint32_t)__cvta_generic_to_shared(p);
}
__device__ __forceinline__ void ldsm_x4(uint32_t* r, uint32_t a) {
    asm volatile("ldmatrix.sync.aligned.m8n8.x4.shared.b16 {%0,%1,%2,%3}, [%4];"
                 : "=r"(r[0]), "=r"(r[1]), "=r"(r[2]), "=r"(r[3]) : "r"(a));
}
__device__ __forceinline__ void ldsm_x4_t(uint32_t* r, uint32_t a) {
    asm volatile("ldmatrix.sync.aligned.m8n8.x4.trans.shared.b16 {%0,%1,%2,%3}, [%4];"
                 : "=r"(r[0]), "=r"(r[1]), "=r"(r[2]), "=r"(r[3]) : "r"(a));
}
__device__ __forceinline__ void mma16816(float* c, const uint32_t* a, const uint32_t* b) {
    asm volatile(
        "mma.sync.aligned.m16n8k16.row.col.f32.f16.f16.f32 "
        "{%0,%1,%2,%3}, {%4,%5,%6,%7}, {%8,%9}, {%0,%1,%2,%3};"
        : "+f"(c[0]), "+f"(c[1]), "+f"(c[2]), "+f"(c[3])
        : "r"(a[0]), "r"(a[1]), "r"(a[2]), "r"(a[3]), "r"(b[0]), "r"(b[1]));
}
__device__ __forceinline__ void cp16(uint32_t dst, const void* src) {
    asm volatile("cp.async.cg.shared.global [%0], [%1], 16;"
                 :: "r"(dst), "l"(src));
}
__device__ __forceinline__ void cp16z(uint32_t dst, const void* src, int sz) {
    asm volatile("cp.async.cg.shared.global [%0], [%1], 16, %2;"
                 :: "r"(dst), "l"(src), "r"(sz));
}
__device__ __forceinline__ void cp_commit() {
    asm volatile("cp.async.commit_group;");
}
template <int N>
__device__ __forceinline__ void cp_wait() {
    asm volatile("cp.async.wait_group %0;" :: "n"(N));
}

// ---------------------------------------------------------------------------
// Prep: deg sqrt/rsqrt + convert W0/W1 to fp16 once.
// ---------------------------------------------------------------------------
__global__ void __launch_bounds__(256) prep_kernel(
    const float* __restrict__ deg,
    const float* __restrict__ W0, const float* __restrict__ W1)
{
    const int i = blockIdx.x * 256 + threadIdx.x;
    if (i < NNODES) {
        float d = deg[i];
        g_sdeg[i]  = sqrtf(d);
        g_isdeg[i] = rsqrtf(d);
    }
    if (i < 256 * 128) g_w0h[i] = __float2half_rn(W0[i]);
    if (i < 128 * 128) g_w1h[i] = __float2half_rn(W1[i]);
}

// ---------------------------------------------------------------------------
// GEMM layer 0: C[NPAD x 128] = A32[M x 256] @ Wh + bias, fp16 out.
// BM=64, BN=128, BK=16, 128 threads, 4 warps (2x2), 32x64 per warp.
// fp32 A cp.async ring + in-smem convert; fp16 B cp.async ring.
// ~39KB smem + 13k regs per CTA -> ~5 CTAs/SM (vs 2 at BM=128).
// ---------------------------------------------------------------------------
template <int K>
__global__ void __launch_bounds__(128) hgemm_f32a(
    const float* __restrict__ A, const __half* __restrict__ Wh,
    const float* __restrict__ bias, __half* __restrict__ C, int M)
{
    constexpr int S  = 4;
    constexpr int AP = 24;    // As row pitch (halves)
    constexpr int BP = 136;   // Bs row pitch (halves)
    constexpr int KT = K / 16;

    __shared__ __half Bs[S][16 * BP];    // 17.4 KB
    __shared__ float  A32[S][64 * 16];   // 16 KB
    __shared__ __half As[2][64 * AP];    // 6 KB

    const int t    = threadIdx.x;
    const int lane = t & 31;
    const int wid  = t >> 5;
    const int warpRow = wid >> 1;        // 0..1
    const int warpCol = wid & 1;         // 0..1
    const int blockRow = blockIdx.x * 64;

    const int a_row = t >> 1;            // 0..63
    const int a_kg  = (t & 1) * 8;       // 0/8
    const int grow  = blockRow + a_row;
    const bool a_valid = (grow < M);

    const int b_r = t >> 3;              // 0..15
    const int b_n = (t & 7) * 16;        // 0..112

    auto issue = [&](int s, int k0) {
        const float* src = A + (size_t)grow * K + k0 + a_kg;
        uint32_t d = smem_u32(&A32[s][a_row * 16 + a_kg]);
        const int sz = a_valid ? 16 : 0;
        cp16z(d,      src,     sz);
        cp16z(d + 16, src + 4, sz);
        const __half* bsrc = Wh + (size_t)(k0 + b_r) * 128 + b_n;
        uint32_t bd = smem_u32(&Bs[s][b_r * BP + b_n]);
        cp16(bd,      bsrc);
        cp16(bd + 16, bsrc + 8);
        cp_commit();
    };

    issue(0, 0);
    issue(1, 16);
    issue(2, 32);

    float acc[2][8][4];
    #pragma unroll
    for (int mt = 0; mt < 2; mt++)
        #pragma unroll
        for (int nt = 0; nt < 8; nt++)
            #pragma unroll
            for (int q = 0; q < 4; q++) acc[mt][nt][q] = 0.0f;

    const int a_lr = lane & 15;
    const int a_lk = (lane >> 4) * 8;
    const int b_lr = (lane & 7) + ((lane >> 3) & 1) * 8;
    const int b_lcg = (lane >> 4) * 8;

    for (int kt = 0; kt < KT; kt++) {
        cp_wait<2>();
        __syncthreads();

        // Issue stage kt+S-1 (its buffer was consumed in iteration kt-1;
        // the barrier above orders those reads before these writes).
        if (kt + S - 1 < KT) issue((kt + S - 1) % S, (kt + S - 1) * 16);
        else                 cp_commit();

        // Convert this stage's fp32 A to fp16 ldmatrix layout.
        const int rb = kt & 1;
        {
            const float* s32 = &A32[kt % S][a_row * 16 + a_kg];
            float4 v0 = *(const float4*)s32;
            float4 v1 = *(const float4*)(s32 + 4);
            __half h8[8];
            h8[0] = __float2half_rn(v0.x); h8[1] = __float2half_rn(v0.y);
            h8[2] = __float2half_rn(v0.z); h8[3] = __float2half_rn(v0.w);
            h8[4] = __float2half_rn(v1.x); h8[5] = __float2half_rn(v1.y);
            h8[6] = __float2half_rn(v1.z); h8[7] = __float2half_rn(v1.w);
            *(uint4*)&As[rb][a_row * AP + a_kg] = *(uint4*)h8;
        }
        __syncthreads();

        uint32_t a[2][4];
        #pragma unroll
        for (int mt = 0; mt < 2; mt++) {
            ldsm_x4(a[mt], smem_u32(
                &As[rb][(warpRow * 32 + mt * 16 + a_lr) * AP + a_lk]));
        }

        uint32_t b[8][2];
        #pragma unroll
        for (int ntp = 0; ntp < 4; ntp++) {
            uint32_t r4[4];
            ldsm_x4_t(r4, smem_u32(
                &Bs[kt % S][b_lr * BP + warpCol * 64 + ntp * 16 + b_lcg]));
            b[ntp * 2 + 0][0] = r4[0]; b[ntp * 2 + 0][1] = r4[1];
            b[ntp * 2 + 1][0] = r4[2]; b[ntp * 2 + 1][1] = r4[3];
        }

        #pragma unroll
        for (int mt = 0; mt < 2; mt++)
            #pragma unroll
            for (int nt = 0; nt < 8; nt++)
                mma16816(acc[mt][nt], a[mt], b[nt]);
    }

    // Epilogue: bias (fp32) -> fp16 half2 stores. Padded scratch: no guards.
    float2 bb[8];
    #pragma unroll
    for (int nt = 0; nt < 8; nt++) {
        const int col = warpCol * 64 + nt * 8 + (lane & 3) * 2;
        bb[nt] = *(const float2*)&bias[col];
    }
    #pragma unroll
    for (int mt = 0; mt < 2; mt++) {
        const int r0 = blockRow + warpRow * 32 + mt * 16 + (lane >> 2);
        const int r1 = r0 + 8;
        #pragma unroll
        for (int nt = 0; nt < 8; nt++) {
            const int col = warpCol * 64 + nt * 8 + (lane & 3) * 2;
            *(__half2*)(C + (size_t)r0 * 128 + col) =
                __floats2half2_rn(acc[mt][nt][0] + bb[nt].x,
                                  acc[mt][nt][1] + bb[nt].y);
            *(__half2*)(C + (size_t)r1 * 128 + col) =
                __floats2half2_rn(acc[mt][nt][2] + bb[nt].x,
                                  acc[mt][nt][3] + bb[nt].y);
        }
    }
}

// ---------------------------------------------------------------------------
// GEMM layer 1: fp16 A (padded buffer), fp16 W ring. BM=64, 4 warps.
// ~30KB smem + 13k regs per CTA -> ~5 CTAs/SM.
// ---------------------------------------------------------------------------
template <int K>
__global__ void __launch_bounds__(128) hgemm_f16a(
    const __half* __restrict__ A, const __half* __restrict__ Wh,
    const float* __restrict__ bias, __half* __restrict__ C)
{
    constexpr int S  = 4;
    constexpr int AP = 24;
    constexpr int BP = 136;
    constexpr int KT = K / 16;

    __shared__ __half As[S][64 * AP];    // 12.3 KB
    __shared__ __half Bs[S][16 * BP];    // 17.4 KB

    const int t    = threadIdx.x;
    const int lane = t & 31;
    const int wid  = t >> 5;
    const int warpRow = wid >> 1;
    const int warpCol = wid & 1;
    const int blockRow = blockIdx.x * 64;

    const int a_row = t >> 1;
    const int a_kg  = (t & 1) * 8;
    const int grow  = blockRow + a_row;

    const int b_r = t >> 3;              // 0..15
    const int b_n = (t & 7) * 16;        // 0..112

    auto issue = [&](int s, int k0) {
        cp16(smem_u32(&As[s][a_row * AP + a_kg]),
             A + (size_t)grow * K + k0 + a_kg);
        const __half* bsrc = Wh + (size_t)(k0 + b_r) * 128 + b_n;
        uint32_t bd = smem_u32(&Bs[s][b_r * BP + b_n]);
        cp16(bd,      bsrc);
        cp16(bd + 16, bsrc + 8);
        cp_commit();
    };

    issue(0, 0);
    issue(1, 16);
    issue(2, 32);

    float acc[2][8][4];
    #pragma unroll
    for (int mt = 0; mt < 2; mt++)
        #pragma unroll
        for (int nt = 0; nt < 8; nt++)
            #pragma unroll
            for (int q = 0; q < 4; q++) acc[mt][nt][q] = 0.0f;

    const int a_lr = lane & 15;
    const int a_lk = (lane >> 4) * 8;
    const int b_lr = (lane & 7) + ((lane >> 3) & 1) * 8;
    const int b_lcg = (lane >> 4) * 8;

    for (int kt = 0; kt < KT; kt++) {
        cp_wait<2>();
        __syncthreads();

        if (kt + S - 1 < KT) issue((kt + S - 1) % S, (kt + S - 1) * 16);
        else                 cp_commit();

        const int rb = kt % S;
        uint32_t a[2][4];
        #pragma unroll
        for (int mt = 0; mt < 2; mt++) {
            ldsm_x4(a[mt], smem_u32(
                &As[rb][(warpRow * 32 + mt * 16 + a_lr) * AP + a_lk]));
        }

        uint32_t b[8][2];
        #pragma unroll
        for (int ntp = 0; ntp < 4; ntp++) {
            uint32_t r4[4];
            ldsm_x4_t(r4, smem_u32(
                &Bs[rb][b_lr * BP + warpCol * 64 + ntp * 16 + b_lcg]));
            b[ntp * 2 + 0][0] = r4[0]; b[ntp * 2 + 0][1] = r4[1];
            b[ntp * 2 + 1][0] = r4[2]; b[ntp * 2 + 1][1] = r4[3];
        }

        #pragma unroll
        for (int mt = 0; mt < 2; mt++)
            #pragma unroll
            for (int nt = 0; nt < 8; nt++)
                mma16816(acc[mt][nt], a[mt], b[nt]);
    }

    float2 bb[8];
    #pragma unroll
    for (int nt = 0; nt < 8; nt++) {
        const int col = warpCol * 64 + nt * 8 + (lane & 3) * 2;
        bb[nt] = *(const float2*)&bias[col];
    }
    #pragma unroll
    for (int mt = 0; mt < 2; mt++) {
        const int r0 = blockRow + warpRow * 32 + mt * 16 + (lane >> 2);
        const int r1 = r0 + 8;
        #pragma unroll
        for (int nt = 0; nt < 8; nt++) {
            const int col = warpCol * 64 + nt * 8 + (lane & 3) * 2;
            *(__half2*)(C + (size_t)r0 * 128 + col) =
                __floats2half2_rn(acc[mt][nt][0] + bb[nt].x,
                                  acc[mt][nt][1] + bb[nt].y);
            *(__half2*)(C + (size_t)r1 * 128 + col) =
                __floats2half2_rn(acc[mt][nt][2] + bb[nt].x,
                                  acc[mt][nt][3] + bb[nt].y);
        }
    }
}

// ---------------------------------------------------------------------------
// Random-walk aggregation + ReLU. One WARP per node, fp16, 8-deep gather
// batching, dual accumulator sets (R14-validated).
// ---------------------------------------------------------------------------
__global__ void __launch_bounds__(256) agg_kernel(
    const __half* __restrict__ hin, __half* __restrict__ hout,
    const int* __restrict__ ends_l,
    const float* __restrict__ sdeg,
    const float* __restrict__ isdeg,
    const float* __restrict__ att_l)
{
    __shared__ int2 sp[ANPB][NSAMP];     // {endpoint idx, half2(w,w) bits}

    const int n0 = blockIdx.x * ANPB;
    const int t  = threadIdx.x;

    #pragma unroll
    for (int i = t; i < ANPB * NSAMP; i += 256) {
        const int nl = i / NSAMP;
        const int s  = i - nl * NSAMP;
        const int k  = s / RWS;
        const int r  = s - k * RWS;
        const int n  = n0 + nl;
        const int e  = ends_l[k * (NNODES * RWS) + n * RWS + r];
        const float w = att_l[k + 1] * (1.0f / RWS) * sdeg[n] * isdeg[e];
        __half2 wh = __float2half2_rn(w);
        int2 p; p.x = e; p.y = *(int*)&wh;
        sp[nl][s] = p;
    }
    __syncthreads();

    const int wid  = t >> 5;             // node within block
    const int lane = t & 31;             // 4 halves (8B) per lane
    const int n    = n0 + wid;
    const __half* lbase = hin + lane * 4;

    __half2 a0, a1, b0, b1;
    {
        const __half2 att0h = __float2half2_rn(att_l[0]);
        uint2 sv = *(const uint2*)(lbase + ((size_t)n << 7));
        a0 = __hmul2(att0h, *(const __half2*)&sv.x);
        a1 = __hmul2(att0h, *(const __half2*)&sv.y);
        b0 = __floats2half2_rn(0.f, 0.f);
        b1 = b0;
    }

    #pragma unroll
    for (int s = 0; s < NSAMP; s += 8) {
        int2  pp[8];
        uint2 vv[8];
        #pragma unroll
        for (int j = 0; j < 8; j++) pp[j] = sp[wid][s + j];
        #pragma unroll
        for (int j = 0; j < 8; j++)
            vv[j] = *(const uint2*)(lbase + ((size_t)pp[j].x << 7));
        #pragma unroll
        for (int j = 0; j < 8; j += 2) {
            const __half2 w0 = *(const __half2*)&pp[j].y;
            const __half2 w1 = *(const __half2*)&pp[j + 1].y;
            a0 = __hfma2(w0, *(const __half2*)&vv[j].x,     a0);
            a1 = __hfma2(w0, *(const __half2*)&vv[j].y,     a1);
            b0 = __hfma2(w1, *(const __half2*)&vv[j + 1].x, b0);
            b1 = __hfma2(w1, *(const __half2*)&vv[j + 1].y, b1);
        }
    }

    float2 u0 = __half22float2(a0), u1 = __half22float2(b0);
    float2 v0 = __half22float2(a1), v1 = __half22float2(b1);
    uint2 o;
    ((__half2*)&o.x)[0] = __floats2half2_rn(fmaxf(u0.x + u1.x, 0.f),
                                            fmaxf(u0.y + u1.y, 0.f));
    ((__half2*)&o.y)[0] = __floats2half2_rn(fmaxf(v0.x + v1.x, 0.f),
                                            fmaxf(v0.y + v1.y, 0.f));
    *(uint2*)(hout + (size_t)n * HDIM + lane * 4) = o;
}

// ---------------------------------------------------------------------------
// Final: logits = h @ W2 + b2 (HMMA, N padded 40->64), fused log_softmax.
// BM=64, 4 warps, warp tile 16x64. Padded cols: bias -1e30 -> never max.
// ---------------------------------------------------------------------------
__global__ void __launch_bounds__(128) final_kernel(
    const __half* __restrict__ h, const float* __restrict__ W2,
    const float* __restrict__ b2, float* __restrict__ out, int M)
{
    constexpr int AP = 136;  // As pitch (rows of 128 halves)
    constexpr int BP = 72;   // Bs pitch (rows of 64 halves)
    __shared__ __half As[64 * AP];
    __shared__ __half Bs[128 * BP];

    const int t    = threadIdx.x;
    const int lane = t & 31;
    const int wid  = t >> 5;
    const int blockRow = blockIdx.x * 64;

    // Stage B: W2 [128 k x 40] -> padded fp16 [128 x 64].
    {
        const int r = t;
        __half h8[8];
        #pragma unroll
        for (int c0 = 0; c0 < 64; c0 += 8) {
            #pragma unroll
            for (int q = 0; q < 8; q++) {
                const int c = c0 + q;
                h8[q] = (c < CDIM) ? __float2half_rn(W2[r * CDIM + c])
                                   : __float2half_rn(0.0f);
            }
            *(uint4*)&Bs[r * BP + c0] = *(uint4*)h8;
        }
    }
    // Stage A: h rows [blockRow..+63] x 128 halves (padded buffer, no guard).
    {
        const int a_row = t >> 1;
        const int kg    = (t & 1) * 64;
        const uint4* src = (const uint4*)(h + (size_t)(blockRow + a_row) * HDIM + kg);
        #pragma unroll
        for (int q = 0; q < 8; q++)
            *(uint4*)&As[a_row * AP + kg + q * 8] = src[q];
    }
    __syncthreads();

    const int a_lr = lane & 15;
    const int a_lk = (lane >> 4) * 8;
    const int b_lr = (lane & 7) + ((lane >> 3) & 1) * 8;
    const int b_lcg = (lane >> 4) * 8;

    float acc[8][4];
    #pragma unroll
    for (int nt = 0; nt < 8; nt++)
        #pragma unroll
        for (int q = 0; q < 4; q++) acc[nt][q] = 0.0f;

    #pragma unroll
    for (int k0 = 0; k0 < HDIM; k0 += 16) {
        uint32_t a[4];
        ldsm_x4(a, smem_u32(&As[(wid * 16 + a_lr) * AP + k0 + a_lk]));

        uint32_t b[8][2];
        #pragma unroll
        for (int ntp = 0; ntp < 4; ntp++) {
            uint32_t r4[4];
            ldsm_x4_t(r4, smem_u32(&Bs[(k0 + b_lr) * BP + ntp * 16 + b_lcg]));
            b[ntp * 2 + 0][0] = r4[0]; b[ntp * 2 + 0][1] = r4[1];
            b[ntp * 2 + 1][0] = r4[2]; b[ntp * 2 + 1][1] = r4[3];
        }

        #pragma unroll
        for (int nt = 0; nt < 8; nt++)
            mma16816(acc[nt], a, b[nt]);
    }

    float v0[8][2], v1[8][2];
    #pragma unroll
    for (int nt = 0; nt < 8; nt++) {
        const int col = nt * 8 + (lane & 3) * 2;
        const float bx = (col     < CDIM) ? b2[col]     : -1e30f;
        const float by = (col + 1 < CDIM) ? b2[col + 1] : -1e30f;
        v0[nt][0] = acc[nt][0] + bx; v0[nt][1] = acc[nt][1] + by;
        v1[nt][0] = acc[nt][2] + bx; v1[nt][1] = acc[nt][3] + by;
    }

    float m0 = -1e30f, m1 = -1e30f;
    #pragma unroll
    for (int nt = 0; nt < 8; nt++) {
        m0 = fmaxf(m0, fmaxf(v0[nt][0], v0[nt][1]));
        m1 = fmaxf(m1, fmaxf(v1[nt][0], v1[nt][1]));
    }
    m0 = fmaxf(m0, __shfl_xor_sync(0xffffffffu, m0, 1));
    m0 = fmaxf(m0, __shfl_xor_sync(0xffffffffu, m0, 2));
    m1 = fmaxf(m1, __shfl_xor_sync(0xffffffffu, m1, 1));
    m1 = fmaxf(m1, __shfl_xor_sync(0xffffffffu, m1, 2));

    float s0 = 0.0f, s1 = 0.0f;
    #pragma unroll
    for (int nt = 0; nt < 8; nt++) {
        s0 += __expf(v0[nt][0] - m0) + __expf(v0[nt][1] - m0);
        s1 += __expf(v1[nt][0] - m1) + __expf(v1[nt][1] - m1);
    }
    s0 += __shfl_xor_sync(0xffffffffu, s0, 1);
    s0 += __shfl_xor_sync(0xffffffffu, s0, 2);
    s1 += __shfl_xor_sync(0xffffffffu, s1, 1);
    s1 += __shfl_xor_sync(0xffffffffu, s1, 2);

    const float lse0 = m0 + __logf(s0);
    const float lse1 = m1 + __logf(s1);

    const int r0 = blockRow + wid * 16 + (lane >> 2);
    const int r1 = r0 + 8;
    #pragma unroll
    for (int nt = 0; nt < 5; nt++) {        // cols 0..39 only
        const int col = nt * 8 + (lane & 3) * 2;
        if (r0 < M) {
            float2 w = make_float2(v0[nt][0] - lse0, v0[nt][1] - lse0);
            *(float2*)(out + (size_t)r0 * CDIM + col) = w;
        }
        if (r1 < M) {
            float2 w = make_float2(v1[nt][0] - lse1, v1[nt][1] - lse1);
            *(float2*)(out + (size_t)r1 * CDIM + col) = w;
        }
    }
}

// ---------------------------------------------------------------------------
// Launch sequence. Inputs: x, degree, ends, att, W0, b0, W1, b1, W2, b2
// ---------------------------------------------------------------------------
extern "C" void kernel_launch(void* const* d_in, const int* in_sizes, int n_in,
                              void* d_out, int out_size)
{
    const float* x   = (const float*)d_in[0];
    const float* deg = (const float*)d_in[1];
    const int*   ends= (const int*)  d_in[2];
    const float* att = (const float*)d_in[3];
    const float* W0  = (const float*)d_in[4];
    const float* b0  = (const float*)d_in[5];
    const float* W1  = (const float*)d_in[6];
    const float* b1  = (const float*)d_in[7];
    const float* W2  = (const float*)d_in[8];
    const float* b2  = (const float*)d_in[9];
    float* out = (float*)d_out;

    __half *bufA, *bufB, *w0h, *w1h;
    float *sdeg, *isdeg;
    cudaGetSymbolAddress((void**)&bufA, g_bufA);
    cudaGetSymbolAddress((void**)&bufB, g_bufB);
    cudaGetSymbolAddress((void**)&w0h,  g_w0h);
    cudaGetSymbolAddress((void**)&w1h,  g_w1h);
    cudaGetSymbolAddress((void**)&sdeg, g_sdeg);
    cudaGetSymbolAddress((void**)&isdeg,g_isdeg);

    const int gridM   = NPAD / 64;                // 1564
    const int gridF   = (NNODES + 63) / 64;       // 1563
    const int gridAgg = NNODES / ANPB;            // 12500

    prep_kernel<<<(NNODES + 255) / 256, 256>>>(deg, W0, W1);
    // Layer 0: h = x @ W0h + b0 -> bufA (fp16)
    hgemm_f32a<256><<<gridM, 128>>>(x, w0h, b0, bufA, NNODES);
    // Agg layer 0: bufA -> bufB (relu'd)
    agg_kernel<<<gridAgg, 256>>>(bufA, bufB,
                                 ends + 0 * (size_t)KHOPS * NNODES * RWS,
                                 sdeg, isdeg, att + 0 * (KHOPS + 1));
    // Layer 1: h = bufB @ W1h + b1 -> bufA
    hgemm_f16a<128><<<gridM, 128>>>(bufB, w1h, b1, bufA);
    // Agg layer 1: bufA -> bufB (relu'd)
    agg_kernel<<<gridAgg, 256>>>(bufA, bufB,
                                 ends + 1 * (size_t)KHOPS * NNODES * RWS,
                                 sdeg, isdeg, att + 1 * (KHOPS + 1));
    // Final: logits + fused log_softmax -> out (tensor cores)
    final_kernel<<<gridF, 128>>>(bufB, W2, b2, out, NNODES);
}